// round 1
// baseline (speedup 1.0000x reference)
#include <cuda_runtime.h>

// Problem constants
#define SQ   256   // query length S
#define MLEN 256   // memory length M
#define BB   8     // batch
#define DD   512   // model dim
#define HH   8     // heads
#define HD   64    // head dim
#define KL   512   // key length = S + M

// Scratch (device globals; allocation-free)
__device__ float g_Q [BB*HH*SQ*HD];   // (b,h,s,hd)        4 MB
__device__ float g_K [BB*HH*KL*HD];   // (b,h,k,hd)        8 MB
__device__ float g_V [BB*HH*KL*HD];   // (b,h,k,hd)        8 MB
__device__ float g_R [HH*KL*HD];      // (h,j,hd)          1 MB
__device__ float g_QK[BB*HH*SQ*KL];   // scores/probs     32 MB
__device__ float g_QR[BB*HH*SQ*KL];   // rel scores       32 MB
__device__ float g_Y [SQ*BB*DD];      // attn out (s,b,d)  4 MB

// ---------------------------------------------------------------------------
// Projection GEMM:  C = A (Mrows x 512) @ W^T (W is 512x512 row-major)
// BM=128, BN=64, BK=16, 256 threads, 8x4 micro-tile.
// MODE 0: Q proj   (A0 = x)
// MODE 1: K proj   (A = concat(memory, x) rows)
// MODE 2: V proj   (same A as 1)
// MODE 3: R proj   (A0 = rel_pos, Mrows=512)
// MODE 4: out GEMM (A = g_Y, C = d_out)
// ---------------------------------------------------------------------------
template<int MODE>
__global__ __launch_bounds__(256)
void gemm_proj(const float* __restrict__ A0, const float* __restrict__ A1,
               const float* __restrict__ W, float* __restrict__ Cext)
{
    __shared__ float As[16][132];   // [k][m] transposed
    __shared__ float Ws[16][68];    // [k][n] transposed

    const int row0 = blockIdx.y * 128;
    const int col0 = blockIdx.x * 64;
    const int tid  = threadIdx.x;
    const int tx   = tid & 15;       // 16 col-groups of 4
    const int ty   = tid >> 4;       // 16 row-groups of 8
    const int lr   = tid >> 2;       // 0..63 load row
    const int lc   = (tid & 3) * 4;  // 0,4,8,12 load col (k)

    float acc[8][4];
    #pragma unroll
    for (int i = 0; i < 8; i++)
        #pragma unroll
        for (int j = 0; j < 4; j++) acc[i][j] = 0.f;

    for (int k0 = 0; k0 < 512; k0 += 16) {
        // A tile: 128 rows x 16 k
        #pragma unroll
        for (int p = 0; p < 2; p++) {
            const int r = row0 + lr + p * 64;
            const float* arow;
            if constexpr (MODE == 1 || MODE == 2) {
                arow = (r < MLEN * BB) ? (A0 + (size_t)r * DD)
                                       : (A1 + (size_t)(r - MLEN * BB) * DD);
            } else if constexpr (MODE == 4) {
                arow = g_Y + (size_t)r * DD;
            } else {
                arow = A0 + (size_t)r * DD;
            }
            float4 av = *reinterpret_cast<const float4*>(arow + k0 + lc);
            As[lc + 0][lr + p * 64] = av.x;
            As[lc + 1][lr + p * 64] = av.y;
            As[lc + 2][lr + p * 64] = av.z;
            As[lc + 3][lr + p * 64] = av.w;
        }
        // W tile: 64 n-rows x 16 k
        {
            float4 wv = *reinterpret_cast<const float4*>(
                W + (size_t)(col0 + lr) * DD + k0 + lc);
            Ws[lc + 0][lr] = wv.x;
            Ws[lc + 1][lr] = wv.y;
            Ws[lc + 2][lr] = wv.z;
            Ws[lc + 3][lr] = wv.w;
        }
        __syncthreads();

        #pragma unroll
        for (int kk = 0; kk < 16; kk++) {
            float a[8], w[4];
            *reinterpret_cast<float4*>(a)     = *reinterpret_cast<const float4*>(&As[kk][ty * 8]);
            *reinterpret_cast<float4*>(a + 4) = *reinterpret_cast<const float4*>(&As[kk][ty * 8 + 4]);
            *reinterpret_cast<float4*>(w)     = *reinterpret_cast<const float4*>(&Ws[kk][tx * 4]);
            #pragma unroll
            for (int i = 0; i < 8; i++)
                #pragma unroll
                for (int j = 0; j < 4; j++)
                    acc[i][j] = fmaf(a[i], w[j], acc[i][j]);
        }
        __syncthreads();
    }

    #pragma unroll
    for (int i = 0; i < 8; i++) {
        const int m = row0 + ty * 8 + i;
        #pragma unroll
        for (int j = 0; j < 4; j++) {
            const int n = col0 + tx * 4 + j;
            const float v = acc[i][j];
            if constexpr (MODE == 0) {
                const int s = m >> 3, b = m & 7, h = n >> 6, hd = n & 63;
                g_Q[((b * HH + h) * SQ + s) * HD + hd] = v;
            } else if constexpr (MODE == 1) {
                const int jj = m >> 3, b = m & 7, h = n >> 6, hd = n & 63;
                g_K[((b * HH + h) * KL + jj) * HD + hd] = v;
            } else if constexpr (MODE == 2) {
                const int jj = m >> 3, b = m & 7, h = n >> 6, hd = n & 63;
                g_V[((b * HH + h) * KL + jj) * HD + hd] = v;
            } else if constexpr (MODE == 3) {
                const int h = n >> 6, hd = n & 63;
                g_R[(h * KL + m) * HD + hd] = v;
            } else {
                Cext[(size_t)m * DD + n] = v;
            }
        }
    }
}

// ---------------------------------------------------------------------------
// Score GEMMs, batched over bh = b*H+h.
// QR_MODE 0: g_QK[q,k] = 0.125 * (Q[q]+u_h) . K[k]
// QR_MODE 1: g_QR[q,j] = 0.125 * (Q[q]+v_h) . R[h,j]
// BM=64, BN=64, BK=16, 256 threads, 4x4 micro-tile, reduction = 64.
// ---------------------------------------------------------------------------
template<int QR_MODE>
__global__ __launch_bounds__(256)
void gemm_scores(const float* __restrict__ bias)
{
    __shared__ float As[16][68];
    __shared__ float Bs[16][68];

    const int bh = blockIdx.z;
    const int h  = bh & 7;
    const int m0 = blockIdx.y * 64;
    const int n0 = blockIdx.x * 64;

    const float* Abase = g_Q + (size_t)bh * SQ * HD;
    const float* Bbase = QR_MODE ? (g_R + (size_t)h * KL * HD)
                                 : (g_K + (size_t)bh * KL * HD);
    float* Cbase = (QR_MODE ? g_QR : g_QK) + (size_t)bh * SQ * KL;

    const int tid = threadIdx.x;
    const int tx  = tid & 15;
    const int ty  = tid >> 4;
    const int lr  = tid >> 2;
    const int lc  = (tid & 3) * 4;

    float acc[4][4];
    #pragma unroll
    for (int i = 0; i < 4; i++)
        #pragma unroll
        for (int j = 0; j < 4; j++) acc[i][j] = 0.f;

    #pragma unroll
    for (int k0 = 0; k0 < 64; k0 += 16) {
        float4 av = *reinterpret_cast<const float4*>(Abase + (m0 + lr) * HD + k0 + lc);
        float4 bv = *reinterpret_cast<const float4*>(bias + h * HD + k0 + lc);
        As[lc + 0][lr] = av.x + bv.x;
        As[lc + 1][lr] = av.y + bv.y;
        As[lc + 2][lr] = av.z + bv.z;
        As[lc + 3][lr] = av.w + bv.w;
        float4 wv = *reinterpret_cast<const float4*>(Bbase + (n0 + lr) * HD + k0 + lc);
        Bs[lc + 0][lr] = wv.x;
        Bs[lc + 1][lr] = wv.y;
        Bs[lc + 2][lr] = wv.z;
        Bs[lc + 3][lr] = wv.w;
        __syncthreads();

        #pragma unroll
        for (int kk = 0; kk < 16; kk++) {
            float a[4], w[4];
            *reinterpret_cast<float4*>(a) = *reinterpret_cast<const float4*>(&As[kk][ty * 4]);
            *reinterpret_cast<float4*>(w) = *reinterpret_cast<const float4*>(&Bs[kk][tx * 4]);
            #pragma unroll
            for (int i = 0; i < 4; i++)
                #pragma unroll
                for (int j = 0; j < 4; j++)
                    acc[i][j] = fmaf(a[i], w[j], acc[i][j]);
        }
        __syncthreads();
    }

    #pragma unroll
    for (int i = 0; i < 4; i++)
        #pragma unroll
        for (int j = 0; j < 4; j++)
            Cbase[(m0 + ty * 4 + i) * KL + n0 + tx * 4 + j] = acc[i][j] * 0.125f;
}

// ---------------------------------------------------------------------------
// Softmax: one warp per (b,h,q) row. Combines QK + gathered QR, applies
// causal mask (k > q+M masked), overwrites g_QK with probabilities.
// ---------------------------------------------------------------------------
__global__ __launch_bounds__(256)
void softmax_k()
{
    const int gw   = (blockIdx.x * blockDim.x + threadIdx.x) >> 5;  // 0..16383
    const int lane = threadIdx.x & 31;
    const int q    = gw & 255;
    const int bh   = gw >> 8;
    const size_t base = ((size_t)bh * SQ + q) * KL;
    const int kmax = q + MLEN;   // last valid key index

    float vals[16];
    float mx = -1e30f;
    #pragma unroll
    for (int i = 0; i < 16; i++) {
        const int k = i * 32 + lane;
        float s;
        if (k <= kmax) {
            s = g_QK[base + k] + g_QR[base + (kmax - k)];
        } else {
            s = -1e30f;
        }
        vals[i] = s;
        mx = fmaxf(mx, s);
    }
    #pragma unroll
    for (int o = 16; o > 0; o >>= 1)
        mx = fmaxf(mx, __shfl_xor_sync(0xffffffffu, mx, o));

    float sum = 0.f;
    #pragma unroll
    for (int i = 0; i < 16; i++) {
        const float e = __expf(vals[i] - mx);   // masked: exp(-huge) -> 0
        vals[i] = e;
        sum += e;
    }
    #pragma unroll
    for (int o = 16; o > 0; o >>= 1)
        sum += __shfl_xor_sync(0xffffffffu, sum, o);

    const float inv = 1.f / sum;
    #pragma unroll
    for (int i = 0; i < 16; i++)
        g_QK[base + i * 32 + lane] = vals[i] * inv;
}

// ---------------------------------------------------------------------------
// PV GEMM, batched over bh: Y(q,hd) = P(q,k) @ V(k,hd), reduction K=512.
// BM=64, BN=64(=HD), BK=16. Writes Y in (s,b,d) layout for the output GEMM.
// ---------------------------------------------------------------------------
__global__ __launch_bounds__(256)
void gemm_pv()
{
    __shared__ float As[16][68];   // probs transposed [k][q]
    __shared__ float Bs[16][68];   // V [k][hd]

    const int bh = blockIdx.y;
    const int b  = bh >> 3;
    const int h  = bh & 7;
    const int m0 = blockIdx.x * 64;

    const float* P = g_QK + (size_t)bh * SQ * KL;
    const float* V = g_V  + (size_t)bh * KL * HD;

    const int tid = threadIdx.x;
    const int tx  = tid & 15;
    const int ty  = tid >> 4;
    const int lr  = tid >> 2;         // P load: 64 rows
    const int lc  = (tid & 3) * 4;    // P load: k offset
    const int vr  = tid >> 4;         // V load: 16 k-rows
    const int vc  = (tid & 15) * 4;   // V load: hd offset

    float acc[4][4];
    #pragma unroll
    for (int i = 0; i < 4; i++)
        #pragma unroll
        for (int j = 0; j < 4; j++) acc[i][j] = 0.f;

    for (int k0 = 0; k0 < KL; k0 += 16) {
        float4 av = *reinterpret_cast<const float4*>(P + (size_t)(m0 + lr) * KL + k0 + lc);
        As[lc + 0][lr] = av.x;
        As[lc + 1][lr] = av.y;
        As[lc + 2][lr] = av.z;
        As[lc + 3][lr] = av.w;
        float4 vv = *reinterpret_cast<const float4*>(V + (size_t)(k0 + vr) * HD + vc);
        *reinterpret_cast<float4*>(&Bs[vr][vc]) = vv;
        __syncthreads();

        #pragma unroll
        for (int kk = 0; kk < 16; kk++) {
            float a[4], w[4];
            *reinterpret_cast<float4*>(a) = *reinterpret_cast<const float4*>(&As[kk][ty * 4]);
            *reinterpret_cast<float4*>(w) = *reinterpret_cast<const float4*>(&Bs[kk][tx * 4]);
            #pragma unroll
            for (int i = 0; i < 4; i++)
                #pragma unroll
                for (int j = 0; j < 4; j++)
                    acc[i][j] = fmaf(a[i], w[j], acc[i][j]);
        }
        __syncthreads();
    }

    #pragma unroll
    for (int i = 0; i < 4; i++) {
        const int q = m0 + ty * 4 + i;
        #pragma unroll
        for (int j = 0; j < 4; j++) {
            const int hd = tx * 4 + j;
            g_Y[((size_t)q * BB + b) * DD + h * HD + hd] = acc[i][j];
        }
    }
}

// ---------------------------------------------------------------------------
extern "C" void kernel_launch(void* const* d_in, const int* in_sizes, int n_in,
                              void* d_out, int out_size)
{
    const float* x    = (const float*)d_in[0];
    const float* mem  = (const float*)d_in[1];
    const float* rel  = (const float*)d_in[2];
    // d_in[3] = attn_mask: pure causal, recomputed in-kernel; unused.
    const float* Wq   = (const float*)d_in[4];
    const float* Wk   = (const float*)d_in[5];
    const float* Wv   = (const float*)d_in[6];
    const float* Wr   = (const float*)d_in[7];
    const float* Wo   = (const float*)d_in[8];
    const float* ub   = (const float*)d_in[9];
    const float* vb   = (const float*)d_in[10];
    float* out = (float*)d_out;

    // Projections
    gemm_proj<0><<<dim3(8, 16), 256>>>(x,   nullptr, Wq, nullptr);  // Q   (2048x512)
    gemm_proj<1><<<dim3(8, 32), 256>>>(mem, x,       Wk, nullptr);  // K   (4096x512)
    gemm_proj<2><<<dim3(8, 32), 256>>>(mem, x,       Wv, nullptr);  // V   (4096x512)
    gemm_proj<3><<<dim3(8, 4),  256>>>(rel, nullptr, Wr, nullptr);  // R   (512x512)

    // Scores: (Q+u).K^T and (Q+v).R^T, batched over 64 (b,h)
    gemm_scores<0><<<dim3(8, 4, 64), 256>>>(ub);
    gemm_scores<1><<<dim3(8, 4, 64), 256>>>(vb);

    // Combine + mask + softmax (in-place into g_QK)
    softmax_k<<<2048, 256>>>();

    // P @ V -> Y (s,b,d)
    gemm_pv<<<dim3(4, 64), 256>>>();

    // Output projection: out = Y @ Wo^T
    gemm_proj<4><<<dim3(8, 16), 256>>>(nullptr, nullptr, Wo, out);
}

// round 4
// speedup vs baseline: 1.7442x; 1.7442x over previous
#include <cuda_runtime.h>

// Problem constants
#define SQ   256   // query length S
#define MLEN 256   // memory length M
#define BB   8     // batch
#define DD   512   // model dim
#define HH   8     // heads
#define HD   64    // head dim
#define KL   512   // key length = S + M

// Scratch (device globals; allocation-free)
__device__ float g_Q [BB*HH*SQ*HD];   // (b,h,s,hd)
__device__ float g_K [BB*HH*KL*HD];   // (b,h,k,hd)
__device__ float g_V [BB*HH*KL*HD];   // (b,h,k,hd)
__device__ float g_R [HH*KL*HD];      // (h,j,hd)
__device__ float g_QK[BB*HH*SQ*KL];   // scores/probs
__device__ float g_QR[BB*HH*SQ*KL];   // rel scores
__device__ float g_Y [SQ*BB*DD];      // attn out (s,b,d)

// ---------------------------------------------------------------------------
// tf32 helpers
// ---------------------------------------------------------------------------
__device__ __forceinline__ unsigned f2tf(float f) {
    unsigned u;
    asm("cvt.rna.tf32.f32 %0, %1;" : "=r"(u) : "f"(f));
    return u;
}

__device__ __forceinline__ void mma8(float* c, const unsigned* a, const unsigned* b) {
    asm("mma.sync.aligned.m16n8k8.row.col.f32.tf32.tf32.f32 "
        "{%0,%1,%2,%3}, {%4,%5,%6,%7}, {%8,%9}, {%0,%1,%2,%3};"
        : "+f"(c[0]), "+f"(c[1]), "+f"(c[2]), "+f"(c[3])
        : "r"(a[0]), "r"(a[1]), "r"(a[2]), "r"(a[3]), "r"(b[0]), "r"(b[1]));
}

__device__ __forceinline__ float4 ldg4(const float* p) {
    return *reinterpret_cast<const float4*>(p);
}

__device__ __forceinline__ uint4 cvt4(float4 v) {
    uint4 u;
    u.x = f2tf(v.x); u.y = f2tf(v.y); u.z = f2tf(v.z); u.w = f2tf(v.w);
    return u;
}

// ---------------------------------------------------------------------------
// Projection GEMM (tensor core):  C = A (Mrows x 512) @ W^T
// BM=128, BN=64, BK=16, 256 threads, 8 warps in 4x2, warp tile 32x32.
// MODE 0: Q, 1: K, 2: V, 3: R, 4: out
// ---------------------------------------------------------------------------
template<int MODE>
__global__ __launch_bounds__(256)
void gemm_proj_tc(const float* __restrict__ A0, const float* __restrict__ A1,
                  const float* __restrict__ W, float* __restrict__ Cext)
{
    __shared__ unsigned As[128][20];   // [m][k], stride 20: conflict-free frags
    __shared__ unsigned Bs[64][20];    // [n][k]

    const int row0 = blockIdx.y * 128;
    const int col0 = blockIdx.x * 64;
    const int tid  = threadIdx.x;
    const int lr   = tid >> 2;        // 0..63
    const int lc   = (tid & 3) * 4;   // 0,4,8,12
    const int warp = tid >> 5;
    const int lane = tid & 31;
    const int g    = lane >> 2;       // 0..7
    const int t    = lane & 3;        // 0..3
    const int wm   = (warp & 3) * 32;
    const int wn   = (warp >> 2) * 32;

    auto aRow = [&](int r) -> const float* {
        if constexpr (MODE == 1 || MODE == 2)
            return (r < MLEN * BB) ? A0 + (size_t)r * DD
                                   : A1 + (size_t)(r - MLEN * BB) * DD;
        else if constexpr (MODE == 4)
            return g_Y + (size_t)r * DD;
        else
            return A0 + (size_t)r * DD;
    };

    float acc[2][4][4];
    #pragma unroll
    for (int i = 0; i < 2; i++)
        #pragma unroll
        for (int j = 0; j < 4; j++)
            #pragma unroll
            for (int l = 0; l < 4; l++) acc[i][j][l] = 0.f;

    float4 rA0 = ldg4(aRow(row0 + lr)      + lc);
    float4 rA1 = ldg4(aRow(row0 + lr + 64) + lc);
    float4 rB  = ldg4(W + (size_t)(col0 + lr) * DD + lc);

    for (int k0 = 0; k0 < DD; k0 += 16) {
        *reinterpret_cast<uint4*>(&As[lr][lc])      = cvt4(rA0);
        *reinterpret_cast<uint4*>(&As[lr + 64][lc]) = cvt4(rA1);
        *reinterpret_cast<uint4*>(&Bs[lr][lc])      = cvt4(rB);
        __syncthreads();

        if (k0 + 16 < DD) {
            rA0 = ldg4(aRow(row0 + lr)      + k0 + 16 + lc);
            rA1 = ldg4(aRow(row0 + lr + 64) + k0 + 16 + lc);
            rB  = ldg4(W + (size_t)(col0 + lr) * DD + k0 + 16 + lc);
        }

        #pragma unroll
        for (int ks = 0; ks < 16; ks += 8) {
            unsigned af[2][4], bf[4][2];
            #pragma unroll
            for (int mt = 0; mt < 2; mt++) {
                const int m = wm + mt * 16;
                af[mt][0] = As[m + g][ks + t];
                af[mt][1] = As[m + g + 8][ks + t];
                af[mt][2] = As[m + g][ks + t + 4];
                af[mt][3] = As[m + g + 8][ks + t + 4];
            }
            #pragma unroll
            for (int nt = 0; nt < 4; nt++) {
                const int n = wn + nt * 8 + g;
                bf[nt][0] = Bs[n][ks + t];
                bf[nt][1] = Bs[n][ks + t + 4];
            }
            #pragma unroll
            for (int mt = 0; mt < 2; mt++)
                #pragma unroll
                for (int nt = 0; nt < 4; nt++)
                    mma8(acc[mt][nt], af[mt], bf[nt]);
        }
        __syncthreads();
    }

    // Epilogue: scatter float2 pairs per MODE
    const int h = col0 >> 6;   // head for MODE 0..3
    #pragma unroll
    for (int mt = 0; mt < 2; mt++) {
        #pragma unroll
        for (int nt = 0; nt < 4; nt++) {
            const int nc = col0 + wn + nt * 8 + 2 * t;
            const int hd = nc & 63;
            #pragma unroll
            for (int half = 0; half < 2; half++) {
                const int m = row0 + wm + mt * 16 + g + half * 8;
                float2 v = make_float2(acc[mt][nt][half * 2], acc[mt][nt][half * 2 + 1]);
                if constexpr (MODE == 0) {
                    const int s = m >> 3, b = m & 7;
                    *reinterpret_cast<float2*>(
                        g_Q + (((size_t)(b * HH + h)) * SQ + s) * HD + hd) = v;
                } else if constexpr (MODE == 1) {
                    const int j = m >> 3, b = m & 7;
                    *reinterpret_cast<float2*>(
                        g_K + (((size_t)(b * HH + h)) * KL + j) * HD + hd) = v;
                } else if constexpr (MODE == 2) {
                    const int j = m >> 3, b = m & 7;
                    *reinterpret_cast<float2*>(
                        g_V + (((size_t)(b * HH + h)) * KL + j) * HD + hd) = v;
                } else if constexpr (MODE == 3) {
                    *reinterpret_cast<float2*>(
                        g_R + ((size_t)h * KL + m) * HD + hd) = v;
                } else {
                    *reinterpret_cast<float2*>(Cext + (size_t)m * DD + nc) = v;
                }
            }
        }
    }
}

// ---------------------------------------------------------------------------
// Score GEMMs (tensor core), batched over bh:
// QR 0: g_QK[q,k] = 0.125 * (Q[q]+u_h) . K[k]
// QR 1: g_QR[q,j] = 0.125 * (Q[q]+v_h) . R[h,j]
// BM=128, BN=64, BK=16, reduction 64.
// ---------------------------------------------------------------------------
template<int QR>
__global__ __launch_bounds__(256)
void gemm_scores_tc(const float* __restrict__ bias)
{
    __shared__ unsigned As[128][20];
    __shared__ unsigned Bs[64][20];

    const int bh = blockIdx.z;
    const int h  = bh & 7;
    const int m0 = blockIdx.y * 128;
    const int n0 = blockIdx.x * 64;

    const float* Abase = g_Q + (size_t)bh * SQ * HD;
    const float* Bbase = QR ? (g_R + (size_t)h * KL * HD)
                            : (g_K + (size_t)bh * KL * HD);
    float* Cbase = (QR ? g_QR : g_QK) + (size_t)bh * SQ * KL;

    const int tid  = threadIdx.x;
    const int lr   = tid >> 2;
    const int lc   = (tid & 3) * 4;
    const int warp = tid >> 5;
    const int lane = tid & 31;
    const int g    = lane >> 2;
    const int t    = lane & 3;
    const int wm   = (warp & 3) * 32;
    const int wn   = (warp >> 2) * 32;

    float acc[2][4][4];
    #pragma unroll
    for (int i = 0; i < 2; i++)
        #pragma unroll
        for (int j = 0; j < 4; j++)
            #pragma unroll
            for (int l = 0; l < 4; l++) acc[i][j][l] = 0.f;

    float4 rA0 = ldg4(Abase + (size_t)(m0 + lr) * HD + lc);
    float4 rA1 = ldg4(Abase + (size_t)(m0 + lr + 64) * HD + lc);
    float4 rB  = ldg4(Bbase + (size_t)(n0 + lr) * HD + lc);
    float4 rU  = ldg4(bias + h * HD + lc);

    #pragma unroll
    for (int k0 = 0; k0 < HD; k0 += 16) {
        float4 a0 = make_float4(rA0.x + rU.x, rA0.y + rU.y, rA0.z + rU.z, rA0.w + rU.w);
        float4 a1 = make_float4(rA1.x + rU.x, rA1.y + rU.y, rA1.z + rU.z, rA1.w + rU.w);
        *reinterpret_cast<uint4*>(&As[lr][lc])      = cvt4(a0);
        *reinterpret_cast<uint4*>(&As[lr + 64][lc]) = cvt4(a1);
        *reinterpret_cast<uint4*>(&Bs[lr][lc])      = cvt4(rB);
        __syncthreads();

        if (k0 + 16 < HD) {
            rA0 = ldg4(Abase + (size_t)(m0 + lr) * HD + k0 + 16 + lc);
            rA1 = ldg4(Abase + (size_t)(m0 + lr + 64) * HD + k0 + 16 + lc);
            rB  = ldg4(Bbase + (size_t)(n0 + lr) * HD + k0 + 16 + lc);
            rU  = ldg4(bias + h * HD + k0 + 16 + lc);
        }

        #pragma unroll
        for (int ks = 0; ks < 16; ks += 8) {
            unsigned af[2][4], bf[4][2];
            #pragma unroll
            for (int mt = 0; mt < 2; mt++) {
                const int m = wm + mt * 16;
                af[mt][0] = As[m + g][ks + t];
                af[mt][1] = As[m + g + 8][ks + t];
                af[mt][2] = As[m + g][ks + t + 4];
                af[mt][3] = As[m + g + 8][ks + t + 4];
            }
            #pragma unroll
            for (int nt = 0; nt < 4; nt++) {
                const int n = wn + nt * 8 + g;
                bf[nt][0] = Bs[n][ks + t];
                bf[nt][1] = Bs[n][ks + t + 4];
            }
            #pragma unroll
            for (int mt = 0; mt < 2; mt++)
                #pragma unroll
                for (int nt = 0; nt < 4; nt++)
                    mma8(acc[mt][nt], af[mt], bf[nt]);
        }
        __syncthreads();
    }

    #pragma unroll
    for (int mt = 0; mt < 2; mt++)
        #pragma unroll
        for (int nt = 0; nt < 4; nt++) {
            const int nc = n0 + wn + nt * 8 + 2 * t;
            #pragma unroll
            for (int half = 0; half < 2; half++) {
                const int m = m0 + wm + mt * 16 + g + half * 8;
                float2 v = make_float2(acc[mt][nt][half * 2] * 0.125f,
                                       acc[mt][nt][half * 2 + 1] * 0.125f);
                *reinterpret_cast<float2*>(Cbase + (size_t)m * KL + nc) = v;
            }
        }
}

// ---------------------------------------------------------------------------
// Softmax: one warp per (b,h,q) row. Combines QK + gathered QR, causal mask,
// overwrites g_QK with probabilities.
// ---------------------------------------------------------------------------
__global__ __launch_bounds__(256)
void softmax_k()
{
    const int gw   = (blockIdx.x * blockDim.x + threadIdx.x) >> 5;
    const int lane = threadIdx.x & 31;
    const int q    = gw & 255;
    const int bh   = gw >> 8;
    const size_t base = ((size_t)bh * SQ + q) * KL;
    const int kmax = q + MLEN;

    float vals[16];
    float mx = -1e30f;
    #pragma unroll
    for (int i = 0; i < 16; i++) {
        const int k = i * 32 + lane;
        float s;
        if (k <= kmax) {
            s = g_QK[base + k] + g_QR[base + (kmax - k)];
        } else {
            s = -1e30f;
        }
        vals[i] = s;
        mx = fmaxf(mx, s);
    }
    #pragma unroll
    for (int o = 16; o > 0; o >>= 1)
        mx = fmaxf(mx, __shfl_xor_sync(0xffffffffu, mx, o));

    float sum = 0.f;
    #pragma unroll
    for (int i = 0; i < 16; i++) {
        const float e = __expf(vals[i] - mx);
        vals[i] = e;
        sum += e;
    }
    #pragma unroll
    for (int o = 16; o > 0; o >>= 1)
        sum += __shfl_xor_sync(0xffffffffu, sum, o);

    const float inv = 1.f / sum;
    #pragma unroll
    for (int i = 0; i < 16; i++)
        g_QK[base + i * 32 + lane] = vals[i] * inv;
}

// ---------------------------------------------------------------------------
// PV GEMM (tensor core), batched over bh: Y(q,hd) = P(q,k) @ V(k,hd).
// BM=128, BN=64, BK=16, reduction 512. Writes Y in (s,b,d) layout.
// ---------------------------------------------------------------------------
__global__ __launch_bounds__(256)
void gemm_pv_tc()
{
    __shared__ unsigned As[128][20];   // P [q][k]
    __shared__ unsigned Vs[16][72];    // V [k][hd], stride 72: conflict-free

    const int bh = blockIdx.y;
    const int b  = bh >> 3;
    const int h  = bh & 7;
    const int m0 = blockIdx.x * 128;

    const float* P = g_QK + (size_t)bh * SQ * KL;
    const float* V = g_V  + (size_t)bh * KL * HD;

    const int tid  = threadIdx.x;
    const int lr   = tid >> 2;
    const int lc   = (tid & 3) * 4;
    const int vr   = tid >> 4;         // 0..15 (k)
    const int vc   = (tid & 15) * 4;   // 0..60 (hd)
    const int warp = tid >> 5;
    const int lane = tid & 31;
    const int g    = lane >> 2;
    const int t    = lane & 3;
    const int wm   = (warp & 3) * 32;
    const int wn   = (warp >> 2) * 32;

    float acc[2][4][4];
    #pragma unroll
    for (int i = 0; i < 2; i++)
        #pragma unroll
        for (int j = 0; j < 4; j++)
            #pragma unroll
            for (int l = 0; l < 4; l++) acc[i][j][l] = 0.f;

    float4 rP0 = ldg4(P + (size_t)(m0 + lr) * KL + lc);
    float4 rP1 = ldg4(P + (size_t)(m0 + lr + 64) * KL + lc);
    float4 rV  = ldg4(V + (size_t)vr * HD + vc);

    for (int k0 = 0; k0 < KL; k0 += 16) {
        *reinterpret_cast<uint4*>(&As[lr][lc])      = cvt4(rP0);
        *reinterpret_cast<uint4*>(&As[lr + 64][lc]) = cvt4(rP1);
        *reinterpret_cast<uint4*>(&Vs[vr][vc])      = cvt4(rV);
        __syncthreads();

        if (k0 + 16 < KL) {
            rP0 = ldg4(P + (size_t)(m0 + lr) * KL + k0 + 16 + lc);
            rP1 = ldg4(P + (size_t)(m0 + lr + 64) * KL + k0 + 16 + lc);
            rV  = ldg4(V + (size_t)(k0 + 16 + vr) * HD + vc);
        }

        #pragma unroll
        for (int ks = 0; ks < 16; ks += 8) {
            unsigned af[2][4], bf[4][2];
            #pragma unroll
            for (int mt = 0; mt < 2; mt++) {
                const int m = wm + mt * 16;
                af[mt][0] = As[m + g][ks + t];
                af[mt][1] = As[m + g + 8][ks + t];
                af[mt][2] = As[m + g][ks + t + 4];
                af[mt][3] = As[m + g + 8][ks + t + 4];
            }
            #pragma unroll
            for (int nt = 0; nt < 4; nt++) {
                const int n = wn + nt * 8 + g;
                bf[nt][0] = Vs[ks + t][n];
                bf[nt][1] = Vs[ks + t + 4][n];
            }
            #pragma unroll
            for (int mt = 0; mt < 2; mt++)
                #pragma unroll
                for (int nt = 0; nt < 4; nt++)
                    mma8(acc[mt][nt], af[mt], bf[nt]);
        }
        __syncthreads();
    }

    #pragma unroll
    for (int mt = 0; mt < 2; mt++)
        #pragma unroll
        for (int nt = 0; nt < 4; nt++) {
            const int hd = wn + nt * 8 + 2 * t;
            #pragma unroll
            for (int half = 0; half < 2; half++) {
                const int q = m0 + wm + mt * 16 + g + half * 8;
                float2 v = make_float2(acc[mt][nt][half * 2], acc[mt][nt][half * 2 + 1]);
                *reinterpret_cast<float2*>(
                    g_Y + ((size_t)q * BB + b) * DD + h * HD + hd) = v;
            }
        }
}

// ---------------------------------------------------------------------------
extern "C" void kernel_launch(void* const* d_in, const int* in_sizes, int n_in,
                              void* d_out, int out_size)
{
    const float* x    = (const float*)d_in[0];
    const float* mem  = (const float*)d_in[1];
    const float* rel  = (const float*)d_in[2];
    // d_in[3] = attn_mask: pure causal, recomputed in-kernel; unused.
    const float* Wq   = (const float*)d_in[4];
    const float* Wk   = (const float*)d_in[5];
    const float* Wv   = (const float*)d_in[6];
    const float* Wr   = (const float*)d_in[7];
    const float* Wo   = (const float*)d_in[8];
    const float* ub   = (const float*)d_in[9];
    const float* vb   = (const float*)d_in[10];
    float* out = (float*)d_out;

    // Projections (tf32 tensor core)
    gemm_proj_tc<0><<<dim3(8, 16), 256>>>(x,   nullptr, Wq, nullptr);  // Q
    gemm_proj_tc<1><<<dim3(8, 32), 256>>>(mem, x,       Wk, nullptr);  // K
    gemm_proj_tc<2><<<dim3(8, 32), 256>>>(mem, x,       Wv, nullptr);  // V
    gemm_proj_tc<3><<<dim3(8, 4),  256>>>(rel, nullptr, Wr, nullptr);  // R

    // Scores: (Q+u).K^T and (Q+v).R^T, batched over 64 (b,h)
    gemm_scores_tc<0><<<dim3(8, 2, 64), 256>>>(ub);
    gemm_scores_tc<1><<<dim3(8, 2, 64), 256>>>(vb);

    // Combine + mask + softmax (in-place into g_QK)
    softmax_k<<<2048, 256>>>();

    // P @ V -> Y (s,b,d)
    gemm_pv_tc<<<dim3(2, 64), 256>>>();

    // Output projection: out = Y @ Wo^T
    gemm_proj_tc<4><<<dim3(8, 16), 256>>>(nullptr, nullptr, Wo, out);
}

// round 6
// speedup vs baseline: 2.2447x; 1.2869x over previous
#include <cuda_runtime.h>

// Problem constants
#define SQ   256   // query length S
#define MLEN 256   // memory length M
#define BB   8     // batch
#define DD   512   // model dim
#define HH   8     // heads
#define HD   64    // head dim
#define KL   512   // key length = S + M

// Scratch (device globals; allocation-free)
__device__ float g_Q [BB*HH*SQ*HD];   // (b,h,s,hd)
__device__ float g_K [BB*HH*KL*HD];   // (b,h,k,hd)
__device__ float g_V [BB*HH*KL*HD];   // (b,h,k,hd)
__device__ float g_R [HH*KL*HD];      // (h,j,hd)
__device__ float g_QK[BB*HH*SQ*KL];   // scores/probs
__device__ float g_QR[BB*HH*SQ*KL];   // rel scores
__device__ float g_Y [SQ*BB*DD];      // attn out (s,b,d)

// ---------------------------------------------------------------------------
// tf32 helpers
// ---------------------------------------------------------------------------
__device__ __forceinline__ unsigned f2tf(float f) {
    unsigned u;
    asm("cvt.rna.tf32.f32 %0, %1;" : "=r"(u) : "f"(f));
    return u;
}

__device__ __forceinline__ void mma8(float* c, const unsigned* a, const unsigned* b) {
    asm("mma.sync.aligned.m16n8k8.row.col.f32.tf32.tf32.f32 "
        "{%0,%1,%2,%3}, {%4,%5,%6,%7}, {%8,%9}, {%0,%1,%2,%3};"
        : "+f"(c[0]), "+f"(c[1]), "+f"(c[2]), "+f"(c[3])
        : "r"(a[0]), "r"(a[1]), "r"(a[2]), "r"(a[3]), "r"(b[0]), "r"(b[1]));
}

__device__ __forceinline__ float4 ldg4(const float* p) {
    return *reinterpret_cast<const float4*>(p);
}

__device__ __forceinline__ uint4 cvt4(float4 v) {
    uint4 u;
    u.x = f2tf(v.x); u.y = f2tf(v.y); u.z = f2tf(v.z); u.w = f2tf(v.w);
    return u;
}

struct ProjSmem {
    unsigned As[128][20];
    unsigned Bs[64][20];
};

// ---------------------------------------------------------------------------
// Projection GEMM body:  C = A (rows x 512) @ W^T
// BM=128, BN=64, BK=16, 256 threads, 8 warps (4x2), warp tile 32x32.
// MODE 0: Q, 1: K, 2: V, 3: R, 4: out
// ---------------------------------------------------------------------------
template<int MODE>
__device__ __forceinline__
void proj_body(ProjSmem& sm, int bx, int by,
               const float* __restrict__ A0, const float* __restrict__ A1,
               const float* __restrict__ W, float* __restrict__ Cext)
{
    const int row0 = by * 128;
    const int col0 = bx * 64;
    const int tid  = threadIdx.x;
    const int lr   = tid >> 2;        // 0..63
    const int lc   = (tid & 3) * 4;   // 0,4,8,12
    const int warp = tid >> 5;
    const int lane = tid & 31;
    const int g    = lane >> 2;       // 0..7
    const int t    = lane & 3;        // 0..3
    const int wm   = (warp & 3) * 32;
    const int wn   = (warp >> 2) * 32;

    auto aRow = [&](int r) -> const float* {
        if constexpr (MODE == 1 || MODE == 2)
            return (r < MLEN * BB) ? A0 + (size_t)r * DD
                                   : A1 + (size_t)(r - MLEN * BB) * DD;
        else if constexpr (MODE == 4)
            return g_Y + (size_t)r * DD;
        else
            return A0 + (size_t)r * DD;
    };

    float acc[2][4][4];
    #pragma unroll
    for (int i = 0; i < 2; i++)
        #pragma unroll
        for (int j = 0; j < 4; j++)
            #pragma unroll
            for (int l = 0; l < 4; l++) acc[i][j][l] = 0.f;

    float4 rA0 = ldg4(aRow(row0 + lr)      + lc);
    float4 rA1 = ldg4(aRow(row0 + lr + 64) + lc);
    float4 rB  = ldg4(W + (size_t)(col0 + lr) * DD + lc);

    for (int k0 = 0; k0 < DD; k0 += 16) {
        *reinterpret_cast<uint4*>(&sm.As[lr][lc])      = cvt4(rA0);
        *reinterpret_cast<uint4*>(&sm.As[lr + 64][lc]) = cvt4(rA1);
        *reinterpret_cast<uint4*>(&sm.Bs[lr][lc])      = cvt4(rB);
        __syncthreads();

        if (k0 + 16 < DD) {
            rA0 = ldg4(aRow(row0 + lr)      + k0 + 16 + lc);
            rA1 = ldg4(aRow(row0 + lr + 64) + k0 + 16 + lc);
            rB  = ldg4(W + (size_t)(col0 + lr) * DD + k0 + 16 + lc);
        }

        #pragma unroll
        for (int ks = 0; ks < 16; ks += 8) {
            unsigned af[2][4], bf[4][2];
            #pragma unroll
            for (int mt = 0; mt < 2; mt++) {
                const int m = wm + mt * 16;
                af[mt][0] = sm.As[m + g][ks + t];
                af[mt][1] = sm.As[m + g + 8][ks + t];
                af[mt][2] = sm.As[m + g][ks + t + 4];
                af[mt][3] = sm.As[m + g + 8][ks + t + 4];
            }
            #pragma unroll
            for (int nt = 0; nt < 4; nt++) {
                const int n = wn + nt * 8 + g;
                bf[nt][0] = sm.Bs[n][ks + t];
                bf[nt][1] = sm.Bs[n][ks + t + 4];
            }
            #pragma unroll
            for (int mt = 0; mt < 2; mt++)
                #pragma unroll
                for (int nt = 0; nt < 4; nt++)
                    mma8(acc[mt][nt], af[mt], bf[nt]);
        }
        __syncthreads();
    }

    const int h = col0 >> 6;
    #pragma unroll
    for (int mt = 0; mt < 2; mt++) {
        #pragma unroll
        for (int nt = 0; nt < 4; nt++) {
            const int nc = col0 + wn + nt * 8 + 2 * t;
            const int hd = nc & 63;
            #pragma unroll
            for (int half = 0; half < 2; half++) {
                const int m = row0 + wm + mt * 16 + g + half * 8;
                float2 v = make_float2(acc[mt][nt][half * 2], acc[mt][nt][half * 2 + 1]);
                if constexpr (MODE == 0) {
                    const int s = m >> 3, b = m & 7;
                    *reinterpret_cast<float2*>(
                        g_Q + (((size_t)(b * HH + h)) * SQ + s) * HD + hd) = v;
                } else if constexpr (MODE == 1) {
                    const int j = m >> 3, b = m & 7;
                    *reinterpret_cast<float2*>(
                        g_K + (((size_t)(b * HH + h)) * KL + j) * HD + hd) = v;
                } else if constexpr (MODE == 2) {
                    const int j = m >> 3, b = m & 7;
                    *reinterpret_cast<float2*>(
                        g_V + (((size_t)(b * HH + h)) * KL + j) * HD + hd) = v;
                } else if constexpr (MODE == 3) {
                    *reinterpret_cast<float2*>(
                        g_R + ((size_t)h * KL + m) * HD + hd) = v;
                } else {
                    *reinterpret_cast<float2*>(Cext + (size_t)m * DD + nc) = v;
                }
            }
        }
    }
}

// Fused Q/K/V/R projections: 672 blocks total.
// [0,128) Q  grid(8x16); [128,384) K grid(8x32); [384,640) V grid(8x32);
// [640,672) R grid(8x4).
__global__ __launch_bounds__(256)
void proj_all(const float* __restrict__ x, const float* __restrict__ mem,
              const float* __restrict__ rel,
              const float* __restrict__ Wq, const float* __restrict__ Wk,
              const float* __restrict__ Wv, const float* __restrict__ Wr)
{
    __shared__ ProjSmem sm;
    const int id = blockIdx.x;
    if (id < 128) {
        proj_body<0>(sm, id & 7, id >> 3, x, nullptr, Wq, nullptr);
    } else if (id < 384) {
        const int l = id - 128;
        proj_body<1>(sm, l & 7, l >> 3, mem, x, Wk, nullptr);
    } else if (id < 640) {
        const int l = id - 384;
        proj_body<2>(sm, l & 7, l >> 3, mem, x, Wv, nullptr);
    } else {
        const int l = id - 640;
        proj_body<3>(sm, l & 7, l >> 3, rel, nullptr, Wr, nullptr);
    }
}

// Output projection (separate launch; depends on g_Y)
__global__ __launch_bounds__(256)
void proj_out(const float* __restrict__ Wo, float* __restrict__ out)
{
    __shared__ ProjSmem sm;
    proj_body<4>(sm, blockIdx.x, blockIdx.y, nullptr, nullptr, Wo, out);
}

// ---------------------------------------------------------------------------
// Fused score GEMMs, grid (8, 2, 128). z<64: QK with bias u; z>=64: QR with v.
// g_QK[q,k] = 0.125*(Q[q]+u_h).K[k] ; g_QR[q,j] = 0.125*(Q[q]+v_h).R[h,j]
// ---------------------------------------------------------------------------
__global__ __launch_bounds__(256)
void scores_all(const float* __restrict__ ub, const float* __restrict__ vb)
{
    __shared__ unsigned As[128][20];
    __shared__ unsigned Bs[64][20];

    const int z  = blockIdx.z;
    const int qr = z >> 6;
    const int bh = z & 63;
    const int h  = bh & 7;
    const int m0 = blockIdx.y * 128;
    const int n0 = blockIdx.x * 64;

    const float* bias  = qr ? vb : ub;
    const float* Abase = g_Q + (size_t)bh * SQ * HD;
    const float* Bbase = qr ? (g_R + (size_t)h * KL * HD)
                            : (g_K + (size_t)bh * KL * HD);
    float* Cbase = (qr ? g_QR : g_QK) + (size_t)bh * SQ * KL;

    const int tid  = threadIdx.x;
    const int lr   = tid >> 2;
    const int lc   = (tid & 3) * 4;
    const int warp = tid >> 5;
    const int lane = tid & 31;
    const int g    = lane >> 2;
    const int t    = lane & 3;
    const int wm   = (warp & 3) * 32;
    const int wn   = (warp >> 2) * 32;

    float acc[2][4][4];
    #pragma unroll
    for (int i = 0; i < 2; i++)
        #pragma unroll
        for (int j = 0; j < 4; j++)
            #pragma unroll
            for (int l = 0; l < 4; l++) acc[i][j][l] = 0.f;

    float4 rA0 = ldg4(Abase + (size_t)(m0 + lr) * HD + lc);
    float4 rA1 = ldg4(Abase + (size_t)(m0 + lr + 64) * HD + lc);
    float4 rB  = ldg4(Bbase + (size_t)(n0 + lr) * HD + lc);
    float4 rU  = ldg4(bias + h * HD + lc);

    #pragma unroll
    for (int k0 = 0; k0 < HD; k0 += 16) {
        float4 a0 = make_float4(rA0.x + rU.x, rA0.y + rU.y, rA0.z + rU.z, rA0.w + rU.w);
        float4 a1 = make_float4(rA1.x + rU.x, rA1.y + rU.y, rA1.z + rU.z, rA1.w + rU.w);
        *reinterpret_cast<uint4*>(&As[lr][lc])      = cvt4(a0);
        *reinterpret_cast<uint4*>(&As[lr + 64][lc]) = cvt4(a1);
        *reinterpret_cast<uint4*>(&Bs[lr][lc])      = cvt4(rB);
        __syncthreads();

        if (k0 + 16 < HD) {
            rA0 = ldg4(Abase + (size_t)(m0 + lr) * HD + k0 + 16 + lc);
            rA1 = ldg4(Abase + (size_t)(m0 + lr + 64) * HD + k0 + 16 + lc);
            rB  = ldg4(Bbase + (size_t)(n0 + lr) * HD + k0 + 16 + lc);
            rU  = ldg4(bias + h * HD + k0 + 16 + lc);
        }

        #pragma unroll
        for (int ks = 0; ks < 16; ks += 8) {
            unsigned af[2][4], bf[4][2];
            #pragma unroll
            for (int mt = 0; mt < 2; mt++) {
                const int m = wm + mt * 16;
                af[mt][0] = As[m + g][ks + t];
                af[mt][1] = As[m + g + 8][ks + t];
                af[mt][2] = As[m + g][ks + t + 4];
                af[mt][3] = As[m + g + 8][ks + t + 4];
            }
            #pragma unroll
            for (int nt = 0; nt < 4; nt++) {
                const int n = wn + nt * 8 + g;
                bf[nt][0] = Bs[n][ks + t];
                bf[nt][1] = Bs[n][ks + t + 4];
            }
            #pragma unroll
            for (int mt = 0; mt < 2; mt++)
                #pragma unroll
                for (int nt = 0; nt < 4; nt++)
                    mma8(acc[mt][nt], af[mt], bf[nt]);
        }
        __syncthreads();
    }

    #pragma unroll
    for (int mt = 0; mt < 2; mt++)
        #pragma unroll
        for (int nt = 0; nt < 4; nt++) {
            const int nc = n0 + wn + nt * 8 + 2 * t;
            #pragma unroll
            for (int half = 0; half < 2; half++) {
                const int m = m0 + wm + mt * 16 + g + half * 8;
                float2 v = make_float2(acc[mt][nt][half * 2] * 0.125f,
                                       acc[mt][nt][half * 2 + 1] * 0.125f);
                *reinterpret_cast<float2*>(Cbase + (size_t)m * KL + nc) = v;
            }
        }
}

// ---------------------------------------------------------------------------
// Softmax: one warp per (b,h,q) row.
// ---------------------------------------------------------------------------
__global__ __launch_bounds__(256)
void softmax_k()
{
    const int gw   = (blockIdx.x * blockDim.x + threadIdx.x) >> 5;
    const int lane = threadIdx.x & 31;
    const int q    = gw & 255;
    const int bh   = gw >> 8;
    const size_t base = ((size_t)bh * SQ + q) * KL;
    const int kmax = q + MLEN;

    float vals[16];
    float mx = -1e30f;
    #pragma unroll
    for (int i = 0; i < 16; i++) {
        const int k = i * 32 + lane;
        float s;
        if (k <= kmax) {
            s = g_QK[base + k] + g_QR[base + (kmax - k)];
        } else {
            s = -1e30f;
        }
        vals[i] = s;
        mx = fmaxf(mx, s);
    }
    #pragma unroll
    for (int o = 16; o > 0; o >>= 1)
        mx = fmaxf(mx, __shfl_xor_sync(0xffffffffu, mx, o));

    float sum = 0.f;
    #pragma unroll
    for (int i = 0; i < 16; i++) {
        const float e = __expf(vals[i] - mx);
        vals[i] = e;
        sum += e;
    }
    #pragma unroll
    for (int o = 16; o > 0; o >>= 1)
        sum += __shfl_xor_sync(0xffffffffu, sum, o);

    const float inv = 1.f / sum;
    #pragma unroll
    for (int i = 0; i < 16; i++)
        g_QK[base + i * 32 + lane] = vals[i] * inv;
}

// ---------------------------------------------------------------------------
// PV GEMM: Y(q,hd) = P(q,k) @ V(k,hd), reduction 512.
// BM=64, BN=64, BK=16, 128 threads, 4 warps (2x2), warp tile 32x32.
// grid (4, 64) -> 256 blocks.
// ---------------------------------------------------------------------------
__global__ __launch_bounds__(128)
void gemm_pv_tc()
{
    __shared__ unsigned As[64][20];    // P [q][k]
    __shared__ unsigned Vs[16][72];    // V [k][hd]

    const int bh = blockIdx.y;
    const int b  = bh >> 3;
    const int h  = bh & 7;
    const int m0 = blockIdx.x * 64;

    const float* P = g_QK + (size_t)bh * SQ * KL;
    const float* V = g_V  + (size_t)bh * KL * HD;

    const int tid  = threadIdx.x;
    const int lr   = tid >> 2;         // 0..31 (P rows, +32 for second)
    const int lc   = (tid & 3) * 4;
    const int vr   = tid >> 4;         // 0..7 (V k-rows, +8 for second)
    const int vc   = (tid & 15) * 4;
    const int warp = tid >> 5;
    const int lane = tid & 31;
    const int g    = lane >> 2;
    const int t    = lane & 3;
    const int wm   = (warp & 1) * 32;
    const int wn   = (warp >> 1) * 32;

    float acc[2][4][4];
    #pragma unroll
    for (int i = 0; i < 2; i++)
        #pragma unroll
        for (int j = 0; j < 4; j++)
            #pragma unroll
            for (int l = 0; l < 4; l++) acc[i][j][l] = 0.f;

    float4 rP0 = ldg4(P + (size_t)(m0 + lr) * KL + lc);
    float4 rP1 = ldg4(P + (size_t)(m0 + lr + 32) * KL + lc);
    float4 rV0 = ldg4(V + (size_t)vr * HD + vc);
    float4 rV1 = ldg4(V + (size_t)(vr + 8) * HD + vc);

    for (int k0 = 0; k0 < KL; k0 += 16) {
        *reinterpret_cast<uint4*>(&As[lr][lc])      = cvt4(rP0);
        *reinterpret_cast<uint4*>(&As[lr + 32][lc]) = cvt4(rP1);
        *reinterpret_cast<uint4*>(&Vs[vr][vc])      = cvt4(rV0);
        *reinterpret_cast<uint4*>(&Vs[vr + 8][vc])  = cvt4(rV1);
        __syncthreads();

        if (k0 + 16 < KL) {
            rP0 = ldg4(P + (size_t)(m0 + lr) * KL + k0 + 16 + lc);
            rP1 = ldg4(P + (size_t)(m0 + lr + 32) * KL + k0 + 16 + lc);
            rV0 = ldg4(V + (size_t)(k0 + 16 + vr) * HD + vc);
            rV1 = ldg4(V + (size_t)(k0 + 24 + vr) * HD + vc);
        }

        #pragma unroll
        for (int ks = 0; ks < 16; ks += 8) {
            unsigned af[2][4], bf[4][2];
            #pragma unroll
            for (int mt = 0; mt < 2; mt++) {
                const int m = wm + mt * 16;
                af[mt][0] = As[m + g][ks + t];
                af[mt][1] = As[m + g + 8][ks + t];
                af[mt][2] = As[m + g][ks + t + 4];
                af[mt][3] = As[m + g + 8][ks + t + 4];
            }
            #pragma unroll
            for (int nt = 0; nt < 4; nt++) {
                const int n = wn + nt * 8 + g;
                bf[nt][0] = Vs[ks + t][n];
                bf[nt][1] = Vs[ks + t + 4][n];
            }
            #pragma unroll
            for (int mt = 0; mt < 2; mt++)
                #pragma unroll
                for (int nt = 0; nt < 4; nt++)
                    mma8(acc[mt][nt], af[mt], bf[nt]);
        }
        __syncthreads();
    }

    #pragma unroll
    for (int mt = 0; mt < 2; mt++)
        #pragma unroll
        for (int nt = 0; nt < 4; nt++) {
            const int hd = wn + nt * 8 + 2 * t;
            #pragma unroll
            for (int half = 0; half < 2; half++) {
                const int q = m0 + wm + mt * 16 + g + half * 8;
                float2 v = make_float2(acc[mt][nt][half * 2], acc[mt][nt][half * 2 + 1]);
                *reinterpret_cast<float2*>(
                    g_Y + ((size_t)q * BB + b) * DD + h * HD + hd) = v;
            }
        }
}

// ---------------------------------------------------------------------------
extern "C" void kernel_launch(void* const* d_in, const int* in_sizes, int n_in,
                              void* d_out, int out_size)
{
    const float* x    = (const float*)d_in[0];
    const float* mem  = (const float*)d_in[1];
    const float* rel  = (const float*)d_in[2];
    // d_in[3] = attn_mask: pure causal, recomputed in-kernel; unused.
    const float* Wq   = (const float*)d_in[4];
    const float* Wk   = (const float*)d_in[5];
    const float* Wv   = (const float*)d_in[6];
    const float* Wr   = (const float*)d_in[7];
    const float* Wo   = (const float*)d_in[8];
    const float* ub   = (const float*)d_in[9];
    const float* vb   = (const float*)d_in[10];
    float* out = (float*)d_out;

    // All projections in one launch (672 blocks)
    proj_all<<<672, 256>>>(x, mem, rel, Wq, Wk, Wv, Wr);

    // Both score GEMMs in one launch (2048 blocks)
    scores_all<<<dim3(8, 2, 128), 256>>>(ub, vb);

    // Combine + mask + softmax (in-place into g_QK)
    softmax_k<<<2048, 256>>>();

    // P @ V -> Y (s,b,d), 256 blocks
    gemm_pv_tc<<<dim3(4, 64), 128>>>();

    // Output projection
    proj_out<<<dim3(8, 16), 256>>>(Wo, out);
}

// round 7
// speedup vs baseline: 2.4662x; 1.0987x over previous
#include <cuda_runtime.h>

// Problem constants
#define SQ   256   // query length S
#define MLEN 256   // memory length M
#define BB   8     // batch
#define DD   512   // model dim
#define HH   8     // heads
#define HD   64    // head dim
#define KL   512   // key length = S + M

// Scratch (device globals; allocation-free)
__device__ float g_Q [BB*HH*SQ*HD];   // (b,h,s,hd)
__device__ float g_K [BB*HH*KL*HD];   // (b,h,k,hd)
__device__ float g_V [BB*HH*KL*HD];   // (b,h,k,hd)
__device__ float g_R [HH*KL*HD];      // (h,j,hd)
__device__ float g_Y [SQ*BB*DD];      // attn out (s,b,d)

// ---------------------------------------------------------------------------
// tf32 helpers
// ---------------------------------------------------------------------------
__device__ __forceinline__ unsigned f2tf(float f) {
    unsigned u;
    asm("cvt.rna.tf32.f32 %0, %1;" : "=r"(u) : "f"(f));
    return u;
}

__device__ __forceinline__ void mma8(float* c, const unsigned* a, const unsigned* b) {
    asm("mma.sync.aligned.m16n8k8.row.col.f32.tf32.tf32.f32 "
        "{%0,%1,%2,%3}, {%4,%5,%6,%7}, {%8,%9}, {%0,%1,%2,%3};"
        : "+f"(c[0]), "+f"(c[1]), "+f"(c[2]), "+f"(c[3])
        : "r"(a[0]), "r"(a[1]), "r"(a[2]), "r"(a[3]), "r"(b[0]), "r"(b[1]));
}

__device__ __forceinline__ float4 ldg4(const float* p) {
    return *reinterpret_cast<const float4*>(p);
}

__device__ __forceinline__ uint4 cvt4(float4 v) {
    uint4 u;
    u.x = f2tf(v.x); u.y = f2tf(v.y); u.z = f2tf(v.z); u.w = f2tf(v.w);
    return u;
}

// ===========================================================================
// Projection GEMM (unchanged from R6): C = A (rows x 512) @ W^T
// BM=128, BN=64, BK=16, 256 threads, 8 warps (4x2), warp tile 32x32.
// MODE 0: Q, 1: K, 2: V, 3: R, 4: out
// ===========================================================================
struct ProjSmem {
    unsigned As[128][20];
    unsigned Bs[64][20];
};

template<int MODE>
__device__ __forceinline__
void proj_body(ProjSmem& sm, int bx, int by,
               const float* __restrict__ A0, const float* __restrict__ A1,
               const float* __restrict__ W, float* __restrict__ Cext)
{
    const int row0 = by * 128;
    const int col0 = bx * 64;
    const int tid  = threadIdx.x;
    const int lr   = tid >> 2;
    const int lc   = (tid & 3) * 4;
    const int warp = tid >> 5;
    const int lane = tid & 31;
    const int g    = lane >> 2;
    const int t    = lane & 3;
    const int wm   = (warp & 3) * 32;
    const int wn   = (warp >> 2) * 32;

    auto aRow = [&](int r) -> const float* {
        if constexpr (MODE == 1 || MODE == 2)
            return (r < MLEN * BB) ? A0 + (size_t)r * DD
                                   : A1 + (size_t)(r - MLEN * BB) * DD;
        else if constexpr (MODE == 4)
            return g_Y + (size_t)r * DD;
        else
            return A0 + (size_t)r * DD;
    };

    float acc[2][4][4];
    #pragma unroll
    for (int i = 0; i < 2; i++)
        #pragma unroll
        for (int j = 0; j < 4; j++)
            #pragma unroll
            for (int l = 0; l < 4; l++) acc[i][j][l] = 0.f;

    float4 rA0 = ldg4(aRow(row0 + lr)      + lc);
    float4 rA1 = ldg4(aRow(row0 + lr + 64) + lc);
    float4 rB  = ldg4(W + (size_t)(col0 + lr) * DD + lc);

    for (int k0 = 0; k0 < DD; k0 += 16) {
        *reinterpret_cast<uint4*>(&sm.As[lr][lc])      = cvt4(rA0);
        *reinterpret_cast<uint4*>(&sm.As[lr + 64][lc]) = cvt4(rA1);
        *reinterpret_cast<uint4*>(&sm.Bs[lr][lc])      = cvt4(rB);
        __syncthreads();

        if (k0 + 16 < DD) {
            rA0 = ldg4(aRow(row0 + lr)      + k0 + 16 + lc);
            rA1 = ldg4(aRow(row0 + lr + 64) + k0 + 16 + lc);
            rB  = ldg4(W + (size_t)(col0 + lr) * DD + k0 + 16 + lc);
        }

        #pragma unroll
        for (int ks = 0; ks < 16; ks += 8) {
            unsigned af[2][4], bf[4][2];
            #pragma unroll
            for (int mt = 0; mt < 2; mt++) {
                const int m = wm + mt * 16;
                af[mt][0] = sm.As[m + g][ks + t];
                af[mt][1] = sm.As[m + g + 8][ks + t];
                af[mt][2] = sm.As[m + g][ks + t + 4];
                af[mt][3] = sm.As[m + g + 8][ks + t + 4];
            }
            #pragma unroll
            for (int nt = 0; nt < 4; nt++) {
                const int n = wn + nt * 8 + g;
                bf[nt][0] = sm.Bs[n][ks + t];
                bf[nt][1] = sm.Bs[n][ks + t + 4];
            }
            #pragma unroll
            for (int mt = 0; mt < 2; mt++)
                #pragma unroll
                for (int nt = 0; nt < 4; nt++)
                    mma8(acc[mt][nt], af[mt], bf[nt]);
        }
        __syncthreads();
    }

    const int h = col0 >> 6;
    #pragma unroll
    for (int mt = 0; mt < 2; mt++) {
        #pragma unroll
        for (int nt = 0; nt < 4; nt++) {
            const int nc = col0 + wn + nt * 8 + 2 * t;
            const int hd = nc & 63;
            #pragma unroll
            for (int half = 0; half < 2; half++) {
                const int m = row0 + wm + mt * 16 + g + half * 8;
                float2 v = make_float2(acc[mt][nt][half * 2], acc[mt][nt][half * 2 + 1]);
                if constexpr (MODE == 0) {
                    const int s = m >> 3, b = m & 7;
                    *reinterpret_cast<float2*>(
                        g_Q + (((size_t)(b * HH + h)) * SQ + s) * HD + hd) = v;
                } else if constexpr (MODE == 1) {
                    const int j = m >> 3, b = m & 7;
                    *reinterpret_cast<float2*>(
                        g_K + (((size_t)(b * HH + h)) * KL + j) * HD + hd) = v;
                } else if constexpr (MODE == 2) {
                    const int j = m >> 3, b = m & 7;
                    *reinterpret_cast<float2*>(
                        g_V + (((size_t)(b * HH + h)) * KL + j) * HD + hd) = v;
                } else if constexpr (MODE == 3) {
                    *reinterpret_cast<float2*>(
                        g_R + ((size_t)h * KL + m) * HD + hd) = v;
                } else {
                    *reinterpret_cast<float2*>(Cext + (size_t)m * DD + nc) = v;
                }
            }
        }
    }
}

__global__ __launch_bounds__(256)
void proj_all(const float* __restrict__ x, const float* __restrict__ mem,
              const float* __restrict__ rel,
              const float* __restrict__ Wq, const float* __restrict__ Wk,
              const float* __restrict__ Wv, const float* __restrict__ Wr)
{
    __shared__ ProjSmem sm;
    const int id = blockIdx.x;
    if (id < 128) {
        proj_body<0>(sm, id & 7, id >> 3, x, nullptr, Wq, nullptr);
    } else if (id < 384) {
        const int l = id - 128;
        proj_body<1>(sm, l & 7, l >> 3, mem, x, Wk, nullptr);
    } else if (id < 640) {
        const int l = id - 384;
        proj_body<2>(sm, l & 7, l >> 3, mem, x, Wv, nullptr);
    } else {
        const int l = id - 640;
        proj_body<3>(sm, l & 7, l >> 3, rel, nullptr, Wr, nullptr);
    }
}

__global__ __launch_bounds__(256)
void proj_out(const float* __restrict__ Wo, float* __restrict__ out)
{
    __shared__ ProjSmem sm;
    proj_body<4>(sm, blockIdx.x, blockIdx.y, nullptr, nullptr, Wo, out);
}

// ===========================================================================
// Fused attention core: scores (QK + shifted QR) + softmax + PV, one kernel.
// Grid (4, 64): x = 64-row query tile, y = bh. 256 threads, 8 warps (4x2).
// Dynamic smem:
//   S  : float [64][516]   score/prob buffer        132096 B
//   Qs : float [64][68]    query tile                17408 B
//   us : float [64], vs : float [64]                   512 B
//   BV : unsigned [64*72]  K/R tile ([n][68]) or V tile ([k][72])  18432 B
// Total 168448 B -> 1 CTA/SM.
// ===========================================================================
#define SST 516   // S row stride (floats)
#define ATTN_SMEM (64*516 + 64*68 + 64 + 64 + 64*72)

__global__ __launch_bounds__(256)
void attn_fused(const float* __restrict__ ub, const float* __restrict__ vb)
{
    extern __shared__ float dsm[];
    float*    S   = dsm;                    // 64*516
    float*    Qs  = dsm + 64 * 516;         // 64*68
    float*    us  = Qs + 64 * 68;           // 64
    float*    vsm = us + 64;                // 64
    unsigned* BV  = (unsigned*)(vsm + 64);  // 64*72

    const int q0 = blockIdx.x * 64;
    const int bh = blockIdx.y;
    const int b  = bh >> 3;
    const int h  = bh & 7;

    const int tid  = threadIdx.x;
    const int warp = tid >> 5;
    const int lane = tid & 31;
    const int g    = lane >> 2;      // 0..7
    const int t    = lane & 3;       // 0..3
    const int wm   = (warp & 3) * 16;
    const int wn   = (warp >> 2) * 32;

    // Tile loader indices: thread covers row (tid>>2), cols (tid&3)*16 + i*4
    const int ldr = tid >> 2;
    const int ldc = (tid & 3) * 16;

    // ---- Load Q tile + biases -------------------------------------------
    {
        const float* Qsrc = g_Q + ((size_t)bh * SQ + q0 + ldr) * HD;
        #pragma unroll
        for (int i = 0; i < 4; i++) {
            float4 v = ldg4(Qsrc + ldc + i * 4);
            *reinterpret_cast<float4*>(&Qs[ldr * 68 + ldc + i * 4]) = v;
        }
        if (tid < 64)       us[tid]        = ub[h * HD + tid];
        else if (tid < 128) vsm[tid - 64]  = vb[h * HD + tid - 128 + 64];
    }
    __syncthreads();

    // ---- Phase 1+2: score GEMMs into smem S -----------------------------
    // PH 0: S[q][k]  = 0.125*(Q+u).K   (direct store)
    // PH 1: S[q][qg+256-j] += 0.125*(Q+v).R  (scatter-add)
    #pragma unroll 1
    for (int ph = 0; ph < 2; ph++) {
        const float* bias = ph ? vsm : us;
        const float* Bsrc = ph ? (g_R + (size_t)h * KL * HD)
                               : (g_K + (size_t)bh * KL * HD);

        // A fragments: (Q + bias) as tf32, 8 ksteps
        unsigned af[8][4];
        #pragma unroll
        for (int ks = 0; ks < 8; ks++) {
            const int c0 = ks * 8 + t;
            const int r0 = wm + g;
            af[ks][0] = f2tf(Qs[r0 * 68 + c0]            + bias[c0]);
            af[ks][1] = f2tf(Qs[(r0 + 8) * 68 + c0]      + bias[c0]);
            af[ks][2] = f2tf(Qs[r0 * 68 + c0 + 4]        + bias[c0 + 4]);
            af[ks][3] = f2tf(Qs[(r0 + 8) * 68 + c0 + 4]  + bias[c0 + 4]);
        }

        float4 rB[4];
        #pragma unroll
        for (int i = 0; i < 4; i++)
            rB[i] = ldg4(Bsrc + (size_t)ldr * HD + ldc + i * 4);

        #pragma unroll 1
        for (int nt0 = 0; nt0 < 8; nt0++) {
            #pragma unroll
            for (int i = 0; i < 4; i++)
                *reinterpret_cast<uint4*>(&BV[ldr * 68 + ldc + i * 4]) = cvt4(rB[i]);
            __syncthreads();

            if (nt0 < 7) {
                #pragma unroll
                for (int i = 0; i < 4; i++)
                    rB[i] = ldg4(Bsrc + (size_t)(nt0 * 64 + 64 + ldr) * HD + ldc + i * 4);
            }

            float acc[4][4];
            #pragma unroll
            for (int j = 0; j < 4; j++)
                #pragma unroll
                for (int l = 0; l < 4; l++) acc[j][l] = 0.f;

            #pragma unroll
            for (int ks = 0; ks < 8; ks++) {
                unsigned bf[4][2];
                #pragma unroll
                for (int nt = 0; nt < 4; nt++) {
                    const int n = wn + nt * 8 + g;
                    bf[nt][0] = BV[n * 68 + ks * 8 + t];
                    bf[nt][1] = BV[n * 68 + ks * 8 + t + 4];
                }
                #pragma unroll
                for (int nt = 0; nt < 4; nt++)
                    mma8(acc[nt], af[ks], bf[nt]);
            }

            const int n0 = nt0 * 64;
            if (ph == 0) {
                #pragma unroll
                for (int nt = 0; nt < 4; nt++) {
                    const int col = n0 + wn + nt * 8 + 2 * t;
                    #pragma unroll
                    for (int half = 0; half < 2; half++) {
                        const int q = wm + g + half * 8;
                        *reinterpret_cast<float2*>(&S[q * SST + col]) =
                            make_float2(acc[nt][half * 2] * 0.125f,
                                        acc[nt][half * 2 + 1] * 0.125f);
                    }
                }
            } else {
                #pragma unroll
                for (int nt = 0; nt < 4; nt++) {
                    const int j = n0 + wn + nt * 8 + 2 * t;
                    #pragma unroll
                    for (int half = 0; half < 2; half++) {
                        const int q  = wm + g + half * 8;
                        const int bk = q0 + q + MLEN - j;   // k for j (even)
                        if (bk >= 0)     S[q * SST + bk]     += 0.125f * acc[nt][half * 2];
                        if (bk - 1 >= 0) S[q * SST + bk - 1] += 0.125f * acc[nt][half * 2 + 1];
                    }
                }
            }
            __syncthreads();
        }
    }

    // ---- Phase 3: softmax in smem (8 warps x 8 rows) --------------------
    #pragma unroll 1
    for (int r = 0; r < 8; r++) {
        const int row  = warp * 8 + r;
        const int kmax = q0 + row + MLEN;
        float* Srow = S + row * SST;

        float vals[16];
        float mx = -1e30f;
        #pragma unroll
        for (int i = 0; i < 16; i++) {
            const int k = i * 32 + lane;
            float s = (k <= kmax) ? Srow[k] : -1e30f;
            vals[i] = s;
            mx = fmaxf(mx, s);
        }
        #pragma unroll
        for (int o = 16; o > 0; o >>= 1)
            mx = fmaxf(mx, __shfl_xor_sync(0xffffffffu, mx, o));

        float sum = 0.f;
        #pragma unroll
        for (int i = 0; i < 16; i++) {
            const float e = __expf(vals[i] - mx);
            vals[i] = e;
            sum += e;
        }
        #pragma unroll
        for (int o = 16; o > 0; o >>= 1)
            sum += __shfl_xor_sync(0xffffffffu, sum, o);

        const float inv = 1.f / sum;
        #pragma unroll
        for (int i = 0; i < 16; i++) {
            const int k = i * 32 + lane;
            Srow[k] = (k <= kmax) ? vals[i] * inv : 0.f;
        }
    }
    __syncthreads();

    // ---- Phase 4: PV (A = probs from smem, B = V tiles) -----------------
    {
        const float* Vsrc = g_V + (size_t)bh * KL * HD;

        float acc[4][4];
        #pragma unroll
        for (int j = 0; j < 4; j++)
            #pragma unroll
            for (int l = 0; l < 4; l++) acc[j][l] = 0.f;

        float4 rV[4];
        #pragma unroll
        for (int i = 0; i < 4; i++)
            rV[i] = ldg4(Vsrc + (size_t)ldr * HD + ldc + i * 4);

        #pragma unroll 1
        for (int kt = 0; kt < 8; kt++) {
            #pragma unroll
            for (int i = 0; i < 4; i++)
                *reinterpret_cast<uint4*>(&BV[ldr * 72 + ldc + i * 4]) = cvt4(rV[i]);
            __syncthreads();

            if (kt < 7) {
                #pragma unroll
                for (int i = 0; i < 4; i++)
                    rV[i] = ldg4(Vsrc + (size_t)(kt * 64 + 64 + ldr) * HD + ldc + i * 4);
            }

            #pragma unroll
            for (int ks = 0; ks < 8; ks++) {
                const int kk = kt * 64 + ks * 8;
                const int r0 = wm + g;
                unsigned af[4];
                af[0] = f2tf(S[r0 * SST + kk + t]);
                af[1] = f2tf(S[(r0 + 8) * SST + kk + t]);
                af[2] = f2tf(S[r0 * SST + kk + t + 4]);
                af[3] = f2tf(S[(r0 + 8) * SST + kk + t + 4]);

                unsigned bf[4][2];
                #pragma unroll
                for (int nt = 0; nt < 4; nt++) {
                    const int n = wn + nt * 8 + g;
                    bf[nt][0] = BV[(ks * 8 + t) * 72 + n];
                    bf[nt][1] = BV[(ks * 8 + t + 4) * 72 + n];
                }
                #pragma unroll
                for (int nt = 0; nt < 4; nt++)
                    mma8(acc[nt], af, bf[nt]);
            }
            __syncthreads();
        }

        #pragma unroll
        for (int nt = 0; nt < 4; nt++) {
            const int hd = wn + nt * 8 + 2 * t;
            #pragma unroll
            for (int half = 0; half < 2; half++) {
                const int q = q0 + wm + g + half * 8;
                *reinterpret_cast<float2*>(
                    &g_Y[((size_t)q * BB + b) * DD + h * HD + hd]) =
                    make_float2(acc[nt][half * 2], acc[nt][half * 2 + 1]);
            }
        }
    }
}

// ---------------------------------------------------------------------------
extern "C" void kernel_launch(void* const* d_in, const int* in_sizes, int n_in,
                              void* d_out, int out_size)
{
    const float* x    = (const float*)d_in[0];
    const float* mem  = (const float*)d_in[1];
    const float* rel  = (const float*)d_in[2];
    // d_in[3] = attn_mask: pure causal, recomputed in-kernel; unused.
    const float* Wq   = (const float*)d_in[4];
    const float* Wk   = (const float*)d_in[5];
    const float* Wv   = (const float*)d_in[6];
    const float* Wr   = (const float*)d_in[7];
    const float* Wo   = (const float*)d_in[8];
    const float* ub   = (const float*)d_in[9];
    const float* vb   = (const float*)d_in[10];
    float* out = (float*)d_out;

    cudaFuncSetAttribute(attn_fused, cudaFuncAttributeMaxDynamicSharedMemorySize,
                         ATTN_SMEM * 4);

    // All projections in one launch (672 blocks)
    proj_all<<<672, 256>>>(x, mem, rel, Wq, Wk, Wv, Wr);

    // Fused scores + softmax + PV (256 blocks, 168 KB smem each)
    attn_fused<<<dim3(4, 64), 256, ATTN_SMEM * 4>>>(ub, vb);

    // Output projection
    proj_out<<<dim3(8, 16), 256>>>(Wo, out);
}